// round 1
// baseline (speedup 1.0000x reference)
#include <cuda_runtime.h>
#include <math.h>

#define Bsz 4
#define Ssz 2048
#define Dsz 512
#define Hn 8
#define HDsz 64

// Scratch (module-load allocated, allowed)
__device__ float g_Qh[Bsz * Ssz * Dsz];   // [B,H,S,HD]
__device__ float g_Kh[Bsz * Ssz * Dsz];   // [B,H,S,HD]
__device__ float g_Vh[Bsz * Ssz * Dsz];   // [B,H,S,HD]
__device__ float g_att[Bsz * Ssz * Dsz];  // concat, [B,S,D]
__device__ float g_lin[Bsz * Ssz * Dsz];  // pre-LN,  [B,S,D]

// ---------------------------------------------------------------------------
// Kernel 1: per-head QKV projections.
// Treat as GEMM X[65536 x 64] @ W^T[64 x 64] + b. Row r = (b*S+s)*H + h maps
// to a contiguous 64-float slice of the input (since D = H*64), so tile loads
// are trivially coalesced. Output goes to [B,H,S,HD] layout.
// grid = (1024, 3), block = 256. blockIdx.y selects q/k/v.
// ---------------------------------------------------------------------------
__global__ __launch_bounds__(256) void proj_kernel(
    const float* __restrict__ q, const float* __restrict__ k,
    const float* __restrict__ v,
    const float* __restrict__ Wq, const float* __restrict__ bq,
    const float* __restrict__ Wk, const float* __restrict__ bk,
    const float* __restrict__ Wv, const float* __restrict__ bv) {
  __shared__ float Ws[64 * 65];
  __shared__ float Xs[64 * 65];

  const float* X;
  const float* W;
  const float* bias;
  float* out;
  int which = blockIdx.y;
  if (which == 0) { X = q; W = Wq; bias = bq; out = g_Qh; }
  else if (which == 1) { X = k; W = Wk; bias = bk; out = g_Kh; }
  else { X = v; W = Wv; bias = bv; out = g_Vh; }

  int r0 = blockIdx.x * 64;
  int tid = threadIdx.x;

  for (int i = tid; i < 64 * 64; i += 256) {
    int rr = i >> 6, cc = i & 63;
    Ws[rr * 65 + cc] = W[i];
    Xs[rr * 65 + cc] = X[(size_t)r0 * 64 + i];
  }
  __syncthreads();

  int ty = tid >> 4, tx = tid & 15;
  float acc[4][4];
#pragma unroll
  for (int i = 0; i < 4; i++)
#pragma unroll
    for (int j = 0; j < 4; j++) acc[i][j] = bias[tx * 4 + j];

#pragma unroll 8
  for (int kk = 0; kk < 64; kk++) {
    float a[4], b[4];
#pragma unroll
    for (int i = 0; i < 4; i++) a[i] = Xs[(ty * 4 + i) * 65 + kk];
#pragma unroll
    for (int j = 0; j < 4; j++) b[j] = Ws[(tx * 4 + j) * 65 + kk];
#pragma unroll
    for (int i = 0; i < 4; i++)
#pragma unroll
      for (int j = 0; j < 4; j++) acc[i][j] += a[i] * b[j];
  }

#pragma unroll
  for (int i = 0; i < 4; i++) {
    int r = r0 + ty * 4 + i;
    int h = r % Hn;
    int bs = r / Hn;          // b*S + s
    int b_ = bs / Ssz;
    int s = bs % Ssz;
    size_t o = ((size_t)(b_ * Hn + h) * Ssz + s) * HDsz + tx * 4;
#pragma unroll
    for (int j = 0; j < 4; j++) out[o + j] = acc[i][j];
  }
}

// ---------------------------------------------------------------------------
// Kernel 2: flash attention, fp32. BM=BN=64, 256 threads (16x16 of 4x4 tiles).
// Online softmax with per-row (m,l) kept redundantly in registers across the
// 16 tx-threads of each row group; reductions via shfl_xor within 16-lane
// groups (tid = ty*16+tx, lane = (ty&1)*16+tx -> xor 1/2/4/8 stays in group).
// Dynamic smem: Qs,Ks,Vs,Ps each 64x65 fp32 = 66,560 B.
// grid = (S/64, B*H) = (32, 32).
// ---------------------------------------------------------------------------
extern __shared__ float sm_attn[];

__global__ __launch_bounds__(256) void attn_kernel() {
  float* Qs = sm_attn;
  float* Ks = sm_attn + 64 * 65;
  float* Vs = sm_attn + 2 * 64 * 65;
  float* Ps = sm_attn + 3 * 64 * 65;

  int bh = blockIdx.y;
  int q0 = blockIdx.x * 64;
  const float* Qp = g_Qh + (size_t)bh * Ssz * HDsz;
  const float* Kp = g_Kh + (size_t)bh * Ssz * HDsz;
  const float* Vp = g_Vh + (size_t)bh * Ssz * HDsz;

  int tid = threadIdx.x, ty = tid >> 4, tx = tid & 15;

  for (int i = tid; i < 64 * 64; i += 256) {
    int rr = i >> 6, cc = i & 63;
    Qs[rr * 65 + cc] = Qp[(size_t)q0 * 64 + i];
  }

  float m_i[4], l_i[4], o[4][4];
#pragma unroll
  for (int i = 0; i < 4; i++) {
    m_i[i] = -1e30f;
    l_i[i] = 0.f;
#pragma unroll
    for (int j = 0; j < 4; j++) o[i][j] = 0.f;
  }
  const float scale = rsqrtf((float)Dsz);  // reference scales by sqrt(D)=sqrt(512)

  for (int t = 0; t < Ssz; t += 64) {
    __syncthreads();  // prev iter's Ps/Vs consumed (and Qs visible on iter 0)
    for (int i = tid; i < 64 * 64; i += 256) {
      int rr = i >> 6, cc = i & 63;
      Ks[rr * 65 + cc] = Kp[(size_t)t * 64 + i];
      Vs[rr * 65 + cc] = Vp[(size_t)t * 64 + i];
    }
    __syncthreads();

    float s[4][4];
#pragma unroll
    for (int i = 0; i < 4; i++)
#pragma unroll
      for (int j = 0; j < 4; j++) s[i][j] = 0.f;

#pragma unroll 4
    for (int kk = 0; kk < 64; kk++) {
      float a[4], b[4];
#pragma unroll
      for (int i = 0; i < 4; i++) a[i] = Qs[(ty * 4 + i) * 65 + kk];
#pragma unroll
      for (int j = 0; j < 4; j++) b[j] = Ks[(tx * 4 + j) * 65 + kk];
#pragma unroll
      for (int i = 0; i < 4; i++)
#pragma unroll
        for (int j = 0; j < 4; j++) s[i][j] += a[i] * b[j];
    }

#pragma unroll
    for (int i = 0; i < 4; i++) {
      float rm = -1e30f;
#pragma unroll
      for (int j = 0; j < 4; j++) {
        s[i][j] *= scale;
        rm = fmaxf(rm, s[i][j]);
      }
#pragma unroll
      for (int off = 1; off < 16; off <<= 1)
        rm = fmaxf(rm, __shfl_xor_sync(0xffffffffu, rm, off));
      float mnew = fmaxf(m_i[i], rm);
      float corr = __expf(m_i[i] - mnew);
      float rs = 0.f;
#pragma unroll
      for (int j = 0; j < 4; j++) {
        float p = __expf(s[i][j] - mnew);
        s[i][j] = p;
        rs += p;
      }
#pragma unroll
      for (int off = 1; off < 16; off <<= 1)
        rs += __shfl_xor_sync(0xffffffffu, rs, off);
      l_i[i] = l_i[i] * corr + rs;
      m_i[i] = mnew;
#pragma unroll
      for (int j = 0; j < 4; j++) {
        o[i][j] *= corr;
        Ps[(ty * 4 + i) * 65 + tx * 4 + j] = s[i][j];
      }
    }
    __syncthreads();

#pragma unroll 4
    for (int jj = 0; jj < 64; jj++) {
      float p[4], vv[4];
#pragma unroll
      for (int i = 0; i < 4; i++) p[i] = Ps[(ty * 4 + i) * 65 + jj];
#pragma unroll
      for (int j = 0; j < 4; j++) vv[j] = Vs[jj * 65 + tx * 4 + j];
#pragma unroll
      for (int i = 0; i < 4; i++)
#pragma unroll
        for (int j = 0; j < 4; j++) o[i][j] += p[i] * vv[j];
    }
  }

  int b_ = bh / Hn, h = bh % Hn;
#pragma unroll
  for (int i = 0; i < 4; i++) {
    int srow = q0 + ty * 4 + i;
    float inv = 1.f / l_i[i];
    size_t off = ((size_t)(b_ * Ssz + srow)) * Dsz + h * HDsz + tx * 4;
#pragma unroll
    for (int j = 0; j < 4; j++) g_att[off + j] = o[i][j] * inv;
  }
}

// ---------------------------------------------------------------------------
// Kernel 3: output projection  lin = concat @ Wo^T + bo.
// Standard 64x64 tiled fp32 GEMM over K=512. grid = (8192/64, 512/64).
// ---------------------------------------------------------------------------
__global__ __launch_bounds__(256) void outproj_kernel(
    const float* __restrict__ Wo, const float* __restrict__ bo) {
  __shared__ float Xs[64 * 65];
  __shared__ float Ws[64 * 65];
  int r0 = blockIdx.x * 64;
  int j0 = blockIdx.y * 64;
  int tid = threadIdx.x, ty = tid >> 4, tx = tid & 15;

  float acc[4][4];
#pragma unroll
  for (int i = 0; i < 4; i++)
#pragma unroll
    for (int j = 0; j < 4; j++) acc[i][j] = bo[j0 + tx * 4 + j];

  for (int k0 = 0; k0 < Dsz; k0 += 64) {
    __syncthreads();
    for (int i = tid; i < 64 * 64; i += 256) {
      int rr = i >> 6, cc = i & 63;
      Xs[rr * 65 + cc] = g_att[(size_t)(r0 + rr) * Dsz + k0 + cc];
      Ws[rr * 65 + cc] = Wo[(size_t)(j0 + rr) * Dsz + k0 + cc];
    }
    __syncthreads();
#pragma unroll 8
    for (int kk = 0; kk < 64; kk++) {
      float a[4], b[4];
#pragma unroll
      for (int i = 0; i < 4; i++) a[i] = Xs[(ty * 4 + i) * 65 + kk];
#pragma unroll
      for (int j = 0; j < 4; j++) b[j] = Ws[(tx * 4 + j) * 65 + kk];
#pragma unroll
      for (int i = 0; i < 4; i++)
#pragma unroll
        for (int j = 0; j < 4; j++) acc[i][j] += a[i] * b[j];
    }
  }
#pragma unroll
  for (int i = 0; i < 4; i++) {
    size_t off = (size_t)(r0 + ty * 4 + i) * Dsz + j0 + tx * 4;
#pragma unroll
    for (int j = 0; j < 4; j++) g_lin[off + j] = acc[i][j];
  }
}

// ---------------------------------------------------------------------------
// Kernel 4: out = q + LayerNorm(lin)*gamma + beta (residual AFTER LN).
// One 128-thread block per row of 512 (float4 per thread).
// ---------------------------------------------------------------------------
__global__ __launch_bounds__(128) void ln_kernel(
    const float* __restrict__ q, const float* __restrict__ gamma,
    const float* __restrict__ beta, float* __restrict__ out) {
  int r = blockIdx.x;
  int tid = threadIdx.x;
  const float4 v = ((const float4*)(g_lin + (size_t)r * Dsz))[tid];

  float sum = v.x + v.y + v.z + v.w;
  float sq = v.x * v.x + v.y * v.y + v.z * v.z + v.w * v.w;
  __shared__ float s1[4], s2[4];
#pragma unroll
  for (int off = 16; off; off >>= 1) {
    sum += __shfl_xor_sync(0xffffffffu, sum, off);
    sq += __shfl_xor_sync(0xffffffffu, sq, off);
  }
  int w = tid >> 5;
  if ((tid & 31) == 0) { s1[w] = sum; s2[w] = sq; }
  __syncthreads();
  sum = s1[0] + s1[1] + s1[2] + s1[3];
  sq = s2[0] + s2[1] + s2[2] + s2[3];

  float mu = sum * (1.0f / Dsz);
  float var = sq * (1.0f / Dsz) - mu * mu;
  float inv = rsqrtf(var + 1e-5f);

  float4 g = ((const float4*)gamma)[tid];
  float4 bt = ((const float4*)beta)[tid];
  float4 qv = ((const float4*)(q + (size_t)r * Dsz))[tid];
  float4 o;
  o.x = qv.x + (v.x - mu) * inv * g.x + bt.x;
  o.y = qv.y + (v.y - mu) * inv * g.y + bt.y;
  o.z = qv.z + (v.z - mu) * inv * g.z + bt.z;
  o.w = qv.w + (v.w - mu) * inv * g.w + bt.w;
  ((float4*)(out + (size_t)r * Dsz))[tid] = o;
}

// ---------------------------------------------------------------------------
extern "C" void kernel_launch(void* const* d_in, const int* in_sizes, int n_in,
                              void* d_out, int out_size) {
  const float* q = (const float*)d_in[0];
  const float* k = (const float*)d_in[1];
  const float* v = (const float*)d_in[2];
  const float* Wq = (const float*)d_in[3];
  const float* bq = (const float*)d_in[4];
  const float* Wk = (const float*)d_in[5];
  const float* bk = (const float*)d_in[6];
  const float* Wv = (const float*)d_in[7];
  const float* bv = (const float*)d_in[8];
  const float* Wo = (const float*)d_in[9];
  const float* bo = (const float*)d_in[10];
  const float* gamma = (const float*)d_in[11];
  const float* beta = (const float*)d_in[12];
  float* out = (float*)d_out;

  const int attn_smem = 4 * 64 * 65 * sizeof(float);  // 66,560 B
  cudaFuncSetAttribute(attn_kernel, cudaFuncAttributeMaxDynamicSharedMemorySize,
                       attn_smem);

  proj_kernel<<<dim3(Bsz * Ssz * Hn / 64, 3), 256>>>(q, k, v, Wq, bq, Wk, bk,
                                                     Wv, bv);
  attn_kernel<<<dim3(Ssz / 64, Bsz * Hn), 256, attn_smem>>>();
  outproj_kernel<<<dim3(Bsz * Ssz / 64, Dsz / 64), 256>>>(Wo, bo);
  ln_kernel<<<Bsz * Ssz, 128>>>(q, gamma, beta, out);
}

// round 2
// speedup vs baseline: 4.7455x; 4.7455x over previous
#include <cuda_runtime.h>
#include <math.h>
#include <stdint.h>

#define Bsz 4
#define Ssz 2048
#define Dsz 512
#define Hn 8
#define HDsz 64

#define LDQ 68
#define LDK 68
#define LDV 72

// Scratch (module-load allocated, allowed)
__device__ float g_Qh[Bsz * Ssz * Dsz];   // [B,H,S,HD]
__device__ float g_Kh[Bsz * Ssz * Dsz];   // [B,H,S,HD]
__device__ float g_Vh[Bsz * Ssz * Dsz];   // [B,H,S,HD]
__device__ float g_att[Bsz * Ssz * Dsz];  // concat, [B,S,D]
__device__ float g_lin[Bsz * Ssz * Dsz];  // pre-LN,  [B,S,D]

// ---------------------------------------------------------------------------
// tf32 helpers
// ---------------------------------------------------------------------------
__device__ __forceinline__ uint32_t f2tf(float x) {
  uint32_t r;
  asm("cvt.rna.tf32.f32 %0, %1;" : "=r"(r) : "f"(x));
  return r;
}
__device__ __forceinline__ float f2tff(float x) {
  return __uint_as_float(f2tf(x));
}

__device__ __forceinline__ void mma_tf32(float& c0, float& c1, float& c2,
                                         float& c3, uint32_t a0, uint32_t a1,
                                         uint32_t a2, uint32_t a3, uint32_t b0,
                                         uint32_t b1) {
  asm volatile(
      "mma.sync.aligned.m16n8k8.row.col.f32.tf32.tf32.f32 "
      "{%0,%1,%2,%3}, {%4,%5,%6,%7}, {%8,%9}, {%0,%1,%2,%3};"
      : "+f"(c0), "+f"(c1), "+f"(c2), "+f"(c3)
      : "r"(a0), "r"(a1), "r"(a2), "r"(a3), "r"(b0), "r"(b1));
}

// ---------------------------------------------------------------------------
// Kernel 1: per-head QKV projections (fp32 SIMT — only ~70us, optimize later).
// ---------------------------------------------------------------------------
__global__ __launch_bounds__(256) void proj_kernel(
    const float* __restrict__ q, const float* __restrict__ k,
    const float* __restrict__ v,
    const float* __restrict__ Wq, const float* __restrict__ bq,
    const float* __restrict__ Wk, const float* __restrict__ bk,
    const float* __restrict__ Wv, const float* __restrict__ bv) {
  __shared__ float Ws[64 * 65];
  __shared__ float Xs[64 * 65];

  const float* X;
  const float* W;
  const float* bias;
  float* out;
  int which = blockIdx.y;
  if (which == 0) { X = q; W = Wq; bias = bq; out = g_Qh; }
  else if (which == 1) { X = k; W = Wk; bias = bk; out = g_Kh; }
  else { X = v; W = Wv; bias = bv; out = g_Vh; }

  int r0 = blockIdx.x * 64;
  int tid = threadIdx.x;

  for (int i = tid; i < 64 * 64; i += 256) {
    int rr = i >> 6, cc = i & 63;
    Ws[rr * 65 + cc] = W[i];
    Xs[rr * 65 + cc] = X[(size_t)r0 * 64 + i];
  }
  __syncthreads();

  int ty = tid >> 4, tx = tid & 15;
  float acc[4][4];
#pragma unroll
  for (int i = 0; i < 4; i++)
#pragma unroll
    for (int j = 0; j < 4; j++) acc[i][j] = bias[tx * 4 + j];

#pragma unroll 8
  for (int kk = 0; kk < 64; kk++) {
    float a[4], b[4];
#pragma unroll
    for (int i = 0; i < 4; i++) a[i] = Xs[(ty * 4 + i) * 65 + kk];
#pragma unroll
    for (int j = 0; j < 4; j++) b[j] = Ws[(tx * 4 + j) * 65 + kk];
#pragma unroll
    for (int i = 0; i < 4; i++)
#pragma unroll
      for (int j = 0; j < 4; j++) acc[i][j] += a[i] * b[j];
  }

#pragma unroll
  for (int i = 0; i < 4; i++) {
    int r = r0 + ty * 4 + i;
    int h = r % Hn;
    int bs = r / Hn;  // b*S + s
    int b_ = bs / Ssz;
    int s = bs % Ssz;
    size_t o = ((size_t)(b_ * Hn + h) * Ssz + s) * HDsz + tx * 4;
#pragma unroll
    for (int j = 0; j < 4; j++) out[o + j] = acc[i][j];
  }
}

// ---------------------------------------------------------------------------
// Kernel 2: flash attention with tf32 mma.sync (m16n8k8).
// BM=BN=64, 128 threads (4 warps x 16 rows). P kept register-resident between
// QK^T and PV via intra-quad shuffles (C-frag -> A-frag relayout).
// Bank-conflict-free fragment loads: LDQ/LDK=68 (banks 4g+t), LDV=72 (8t+g).
// grid = (S/64, B*H) = (32, 32). Dynamic smem = 53,248 B.
// ---------------------------------------------------------------------------
extern __shared__ float smx[];

__global__ __launch_bounds__(128) void attn_mma_kernel() {
  float* Qs = smx;                  // 64 x LDQ
  float* Ks = Qs + 64 * LDQ;        // 64 x LDK
  float* Vs = Ks + 64 * LDK;        // 64 x LDV

  int bh = blockIdx.y;
  int q0 = blockIdx.x * 64;
  const float* Qp = g_Qh + (size_t)bh * Ssz * HDsz;
  const float* Kp = g_Kh + (size_t)bh * Ssz * HDsz;
  const float* Vp = g_Vh + (size_t)bh * Ssz * HDsz;

  int tid = threadIdx.x;
  int w = tid >> 5;
  int lane = tid & 31;
  int g = lane >> 2;   // groupID (row within fragment)
  int tq = lane & 3;   // threadID in group

  const float scale = 0.044194173824159216f;  // 1/sqrt(512)

  // Load Q tile (scaled + tf32-rounded)
  {
    const float4* Qg = (const float4*)(Qp + (size_t)q0 * HDsz);
    for (int i = tid; i < 1024; i += 128) {
      float4 vq = Qg[i];
      int row = i >> 4, c = (i & 15) * 4;
      float* d = Qs + row * LDQ + c;
      d[0] = f2tff(vq.x * scale);
      d[1] = f2tff(vq.y * scale);
      d[2] = f2tff(vq.z * scale);
      d[3] = f2tff(vq.w * scale);
    }
  }

  float O[8][4];
#pragma unroll
  for (int nb = 0; nb < 8; nb++)
#pragma unroll
    for (int c = 0; c < 4; c++) O[nb][c] = 0.f;
  float m0 = -1e30f, m1 = -1e30f, l0 = 0.f, l1 = 0.f;

  for (int t = 0; t < Ssz; t += 64) {
    __syncthreads();  // previous tile's Ks/Vs fully consumed (Qs visible it.0)
    {
      const float4* Kg = (const float4*)(Kp + (size_t)t * HDsz);
      const float4* Vg = (const float4*)(Vp + (size_t)t * HDsz);
      for (int i = tid; i < 1024; i += 128) {
        int row = i >> 4, c = (i & 15) * 4;
        float4 kv = Kg[i];
        float* dk = Ks + row * LDK + c;
        dk[0] = f2tff(kv.x); dk[1] = f2tff(kv.y);
        dk[2] = f2tff(kv.z); dk[3] = f2tff(kv.w);
        float4 vv = Vg[i];
        float* dv = Vs + row * LDV + c;
        dv[0] = f2tff(vv.x); dv[1] = f2tff(vv.y);
        dv[2] = f2tff(vv.z); dv[3] = f2tff(vv.w);
      }
    }
    __syncthreads();

    // ---- S = Q K^T (per warp: 16 x 64) ----
    float s[8][4];
#pragma unroll
    for (int nb = 0; nb < 8; nb++)
#pragma unroll
      for (int c = 0; c < 4; c++) s[nb][c] = 0.f;

#pragma unroll
    for (int kc = 0; kc < 8; kc++) {
      const float* qb = Qs + (w * 16 + g) * LDQ + kc * 8 + tq;
      uint32_t a0 = __float_as_uint(qb[0]);
      uint32_t a1 = __float_as_uint(qb[8 * LDQ]);
      uint32_t a2 = __float_as_uint(qb[4]);
      uint32_t a3 = __float_as_uint(qb[8 * LDQ + 4]);
#pragma unroll
      for (int nb = 0; nb < 8; nb++) {
        const float* kb = Ks + (nb * 8 + g) * LDK + kc * 8 + tq;
        uint32_t b0 = __float_as_uint(kb[0]);
        uint32_t b1 = __float_as_uint(kb[4]);
        mma_tf32(s[nb][0], s[nb][1], s[nb][2], s[nb][3], a0, a1, a2, a3, b0,
                 b1);
      }
    }

    // ---- online softmax (rows g and g+8, spread across 4 lanes/quad) ----
    float rm0 = -1e30f, rm1 = -1e30f;
#pragma unroll
    for (int nb = 0; nb < 8; nb++) {
      rm0 = fmaxf(rm0, fmaxf(s[nb][0], s[nb][1]));
      rm1 = fmaxf(rm1, fmaxf(s[nb][2], s[nb][3]));
    }
    rm0 = fmaxf(rm0, __shfl_xor_sync(0xffffffffu, rm0, 1));
    rm0 = fmaxf(rm0, __shfl_xor_sync(0xffffffffu, rm0, 2));
    rm1 = fmaxf(rm1, __shfl_xor_sync(0xffffffffu, rm1, 1));
    rm1 = fmaxf(rm1, __shfl_xor_sync(0xffffffffu, rm1, 2));

    float mn0 = fmaxf(m0, rm0), mn1 = fmaxf(m1, rm1);
    float cr0 = __expf(m0 - mn0), cr1 = __expf(m1 - mn1);
    float rs0 = 0.f, rs1 = 0.f;
#pragma unroll
    for (int nb = 0; nb < 8; nb++) {
      s[nb][0] = __expf(s[nb][0] - mn0);
      s[nb][1] = __expf(s[nb][1] - mn0);
      s[nb][2] = __expf(s[nb][2] - mn1);
      s[nb][3] = __expf(s[nb][3] - mn1);
      rs0 += s[nb][0] + s[nb][1];
      rs1 += s[nb][2] + s[nb][3];
    }
    rs0 += __shfl_xor_sync(0xffffffffu, rs0, 1);
    rs0 += __shfl_xor_sync(0xffffffffu, rs0, 2);
    rs1 += __shfl_xor_sync(0xffffffffu, rs1, 1);
    rs1 += __shfl_xor_sync(0xffffffffu, rs1, 2);

    l0 = l0 * cr0 + rs0;
    l1 = l1 * cr1 + rs1;
    m0 = mn0;
    m1 = mn1;

#pragma unroll
    for (int nb = 0; nb < 8; nb++) {
      O[nb][0] *= cr0; O[nb][1] *= cr0;
      O[nb][2] *= cr1; O[nb][3] *= cr1;
      // round P to tf32 in place (bits stay valid fp32)
      s[nb][0] = f2tff(s[nb][0]);
      s[nb][1] = f2tff(s[nb][1]);
      s[nb][2] = f2tff(s[nb][2]);
      s[nb][3] = f2tff(s[nb][3]);
    }

    // ---- O += P V. A-frags built from S accum frags via intra-quad shfl ----
    int srcA = (lane & ~3) | (tq >> 1);
    int srcB = srcA + 2;
#pragma unroll
    for (int kc = 0; kc < 8; kc++) {
      float x0a = __shfl_sync(0xffffffffu, s[kc][0], srcA);
      float x1a = __shfl_sync(0xffffffffu, s[kc][1], srcA);
      float x0b = __shfl_sync(0xffffffffu, s[kc][0], srcB);
      float x1b = __shfl_sync(0xffffffffu, s[kc][1], srcB);
      float y0a = __shfl_sync(0xffffffffu, s[kc][2], srcA);
      float y1a = __shfl_sync(0xffffffffu, s[kc][3], srcA);
      float y0b = __shfl_sync(0xffffffffu, s[kc][2], srcB);
      float y1b = __shfl_sync(0xffffffffu, s[kc][3], srcB);
      uint32_t a0 = __float_as_uint((tq & 1) ? x1a : x0a);
      uint32_t a2 = __float_as_uint((tq & 1) ? x1b : x0b);
      uint32_t a1 = __float_as_uint((tq & 1) ? y1a : y0a);
      uint32_t a3 = __float_as_uint((tq & 1) ? y1b : y0b);
#pragma unroll
      for (int nb = 0; nb < 8; nb++) {
        const float* vb = Vs + (kc * 8 + tq) * LDV + nb * 8 + g;
        uint32_t b0 = __float_as_uint(vb[0]);
        uint32_t b1 = __float_as_uint(vb[4 * LDV]);
        mma_tf32(O[nb][0], O[nb][1], O[nb][2], O[nb][3], a0, a1, a2, a3, b0,
                 b1);
      }
    }
  }

  // ---- epilogue: normalize and write [B,S,D] concat layout ----
  int b_ = bh >> 3, h = bh & 7;
  float inv0 = 1.f / l0, inv1 = 1.f / l1;
  int r0g = q0 + w * 16 + g;
  size_t base0 = ((size_t)(b_ * Ssz + r0g)) * Dsz + h * 64;
  size_t base1 = base0 + (size_t)8 * Dsz;
#pragma unroll
  for (int nb = 0; nb < 8; nb++) {
    *(float2*)(g_att + base0 + nb * 8 + 2 * tq) =
        make_float2(O[nb][0] * inv0, O[nb][1] * inv0);
    *(float2*)(g_att + base1 + nb * 8 + 2 * tq) =
        make_float2(O[nb][2] * inv1, O[nb][3] * inv1);
  }
}

// ---------------------------------------------------------------------------
// Kernel 3: output projection lin = concat @ Wo^T + bo, tf32 mma.sync.
// BM=64, BN=64, K-loop over 512 in 64 chunks. 128 threads.
// grid = (8192/64, 512/64) = (128, 8).
// ---------------------------------------------------------------------------
__global__ __launch_bounds__(128) void outproj_mma_kernel(
    const float* __restrict__ Wo, const float* __restrict__ bo) {
  __shared__ float Xs[64 * LDQ];
  __shared__ float Ws[64 * LDK];
  int r0 = blockIdx.x * 64;
  int j0 = blockIdx.y * 64;
  int tid = threadIdx.x;
  int w = tid >> 5;
  int lane = tid & 31;
  int g = lane >> 2, tq = lane & 3;

  float acc[8][4];
#pragma unroll
  for (int nb = 0; nb < 8; nb++) {
    float b0v = bo[j0 + nb * 8 + 2 * tq];
    float b1v = bo[j0 + nb * 8 + 2 * tq + 1];
    acc[nb][0] = b0v; acc[nb][1] = b1v;
    acc[nb][2] = b0v; acc[nb][3] = b1v;
  }

  for (int k0 = 0; k0 < Dsz; k0 += 64) {
    __syncthreads();
    for (int i = tid; i < 1024; i += 128) {
      int row = i >> 4, c = (i & 15) * 4;
      float4 xv = *(const float4*)(g_att + (size_t)(r0 + row) * Dsz + k0 + c);
      float* dx = Xs + row * LDQ + c;
      dx[0] = f2tff(xv.x); dx[1] = f2tff(xv.y);
      dx[2] = f2tff(xv.z); dx[3] = f2tff(xv.w);
      float4 wv = *(const float4*)(Wo + (size_t)(j0 + row) * Dsz + k0 + c);
      float* dw = Ws + row * LDK + c;
      dw[0] = f2tff(wv.x); dw[1] = f2tff(wv.y);
      dw[2] = f2tff(wv.z); dw[3] = f2tff(wv.w);
    }
    __syncthreads();

#pragma unroll
    for (int kc = 0; kc < 8; kc++) {
      const float* xb = Xs + (w * 16 + g) * LDQ + kc * 8 + tq;
      uint32_t a0 = __float_as_uint(xb[0]);
      uint32_t a1 = __float_as_uint(xb[8 * LDQ]);
      uint32_t a2 = __float_as_uint(xb[4]);
      uint32_t a3 = __float_as_uint(xb[8 * LDQ + 4]);
#pragma unroll
      for (int nb = 0; nb < 8; nb++) {
        const float* wb = Ws + (nb * 8 + g) * LDK + kc * 8 + tq;
        uint32_t b0 = __float_as_uint(wb[0]);
        uint32_t b1 = __float_as_uint(wb[4]);
        mma_tf32(acc[nb][0], acc[nb][1], acc[nb][2], acc[nb][3], a0, a1, a2,
                 a3, b0, b1);
      }
    }
  }

  int rg = r0 + w * 16 + g;
  size_t base0 = (size_t)rg * Dsz + j0;
  size_t base1 = base0 + (size_t)8 * Dsz;
#pragma unroll
  for (int nb = 0; nb < 8; nb++) {
    *(float2*)(g_lin + base0 + nb * 8 + 2 * tq) =
        make_float2(acc[nb][0], acc[nb][1]);
    *(float2*)(g_lin + base1 + nb * 8 + 2 * tq) =
        make_float2(acc[nb][2], acc[nb][3]);
  }
}

// ---------------------------------------------------------------------------
// Kernel 4: out = q + LayerNorm(lin)*gamma + beta (residual AFTER LN).
// ---------------------------------------------------------------------------
__global__ __launch_bounds__(128) void ln_kernel(
    const float* __restrict__ q, const float* __restrict__ gamma,
    const float* __restrict__ beta, float* __restrict__ out) {
  int r = blockIdx.x;
  int tid = threadIdx.x;
  const float4 v = ((const float4*)(g_lin + (size_t)r * Dsz))[tid];

  float sum = v.x + v.y + v.z + v.w;
  float sq = v.x * v.x + v.y * v.y + v.z * v.z + v.w * v.w;
  __shared__ float s1[4], s2[4];
#pragma unroll
  for (int off = 16; off; off >>= 1) {
    sum += __shfl_xor_sync(0xffffffffu, sum, off);
    sq += __shfl_xor_sync(0xffffffffu, sq, off);
  }
  int w = tid >> 5;
  if ((tid & 31) == 0) { s1[w] = sum; s2[w] = sq; }
  __syncthreads();
  sum = s1[0] + s1[1] + s1[2] + s1[3];
  sq = s2[0] + s2[1] + s2[2] + s2[3];

  float mu = sum * (1.0f / Dsz);
  float var = sq * (1.0f / Dsz) - mu * mu;
  float inv = rsqrtf(var + 1e-5f);

  float4 gm = ((const float4*)gamma)[tid];
  float4 bt = ((const float4*)beta)[tid];
  float4 qv = ((const float4*)(q + (size_t)r * Dsz))[tid];
  float4 o;
  o.x = qv.x + (v.x - mu) * inv * gm.x + bt.x;
  o.y = qv.y + (v.y - mu) * inv * gm.y + bt.y;
  o.z = qv.z + (v.z - mu) * inv * gm.z + bt.z;
  o.w = qv.w + (v.w - mu) * inv * gm.w + bt.w;
  ((float4*)(out + (size_t)r * Dsz))[tid] = o;
}

// ---------------------------------------------------------------------------
extern "C" void kernel_launch(void* const* d_in, const int* in_sizes, int n_in,
                              void* d_out, int out_size) {
  const float* q = (const float*)d_in[0];
  const float* k = (const float*)d_in[1];
  const float* v = (const float*)d_in[2];
  const float* Wq = (const float*)d_in[3];
  const float* bq = (const float*)d_in[4];
  const float* Wk = (const float*)d_in[5];
  const float* bk = (const float*)d_in[6];
  const float* Wv = (const float*)d_in[7];
  const float* bv = (const float*)d_in[8];
  const float* Wo = (const float*)d_in[9];
  const float* bo = (const float*)d_in[10];
  const float* gamma = (const float*)d_in[11];
  const float* beta = (const float*)d_in[12];
  float* out = (float*)d_out;

  const int attn_smem = (64 * LDQ + 64 * LDK + 64 * LDV) * sizeof(float);
  cudaFuncSetAttribute(attn_mma_kernel,
                       cudaFuncAttributeMaxDynamicSharedMemorySize, attn_smem);

  proj_kernel<<<dim3(Bsz * Ssz * Hn / 64, 3), 256>>>(q, k, v, Wq, bq, Wk, bk,
                                                     Wv, bv);
  attn_mma_kernel<<<dim3(Ssz / 64, Bsz * Hn), 128, attn_smem>>>();
  outproj_mma_kernel<<<dim3(Bsz * Ssz / 64, Dsz / 64), 128>>>(Wo, bo);
  ln_kernel<<<Bsz * Ssz, 128>>>(q, gamma, beta, out);
}